// round 3
// baseline (speedup 1.0000x reference)
#include <cuda_runtime.h>
#include <cuda_bf16.h>

#define NN 131072      // nodes
#define NE 2097152     // edges
#define F_IN 32
#define HID 64
#define G_FEAT 16
#define NG 1024        // graphs
#define BN_EPS 1e-5f

// ---------------- scratch ------------------------------------------------------
__device__ float  g_dinv[NN];                 // deg -> dinv_sqrt (in place)
__device__ float4 g_xw[NN * 16];              // xw' = (X@W)*dinv  (per layer)
__device__ float4 g_agg[NN * 16];             // accumulator (init = xw')
__device__ float g_sum1[HID], g_ss1[HID];
__device__ float g_sum2[HID], g_ss2[HID];
__device__ float g_scale1[HID], g_shift1[HID];
__device__ float g_scale2[HID], g_shift2[HID];
__device__ float g_pool[NG * HID];
__device__ float g_cnt[NG];

// ---------------- helpers -----------------------------------------------------
__device__ __forceinline__ void red_add_v4(float* addr, float4 v) {
    asm volatile("red.global.add.v4.f32 [%0], {%1, %2, %3, %4};"
                 :: "l"(addr), "f"(v.x), "f"(v.y), "f"(v.z), "f"(v.w)
                 : "memory");
}

// ---------------- kernels ------------------------------------------------------

// dinv[i] = 1.0 (self-loop contribution to degree)
__global__ void k_fill_ones() {
    int i = blockIdx.x * blockDim.x + threadIdx.x;
    g_dinv[i] = 1.0f;
}

// deg[dst] += 1 per edge
__global__ void k_degree(const int* __restrict__ dst) {
    int e = blockIdx.x * blockDim.x + threadIdx.x;
    atomicAdd(&g_dinv[dst[e]], 1.0f);
}

// xw' = (x @ W1) * dinv ; also init g_agg = xw' ; folds deg->rsqrt conversion
__global__ void k_gemm1(const float* __restrict__ x, const float* __restrict__ W) {
    __shared__ float Ws[F_IN * HID];
    for (int i = threadIdx.x; i < F_IN * HID; i += blockDim.x) Ws[i] = W[i];
    __syncthreads();
    int node = blockIdx.x * blockDim.x + threadIdx.x;

    float di = rsqrtf(g_dinv[node]);   // g_dinv currently holds degree
    g_dinv[node] = di;

    float xr[F_IN];
    const float4* xp = (const float4*)(x + (size_t)node * F_IN);
#pragma unroll
    for (int k = 0; k < F_IN / 4; k++) {
        float4 v = xp[k];
        xr[4 * k + 0] = v.x; xr[4 * k + 1] = v.y;
        xr[4 * k + 2] = v.z; xr[4 * k + 3] = v.w;
    }
#pragma unroll
    for (int j4 = 0; j4 < HID / 4; j4++) {
        float4 acc = make_float4(0.f, 0.f, 0.f, 0.f);
#pragma unroll
        for (int k = 0; k < F_IN; k++) {
            float xv = xr[k];
            const float* w = &Ws[k * HID + 4 * j4];
            acc.x += xv * w[0]; acc.y += xv * w[1];
            acc.z += xv * w[2]; acc.w += xv * w[3];
        }
        acc.x *= di; acc.y *= di; acc.z *= di; acc.w *= di;
        g_xw[(size_t)node * 16 + j4]  = acc;
        g_agg[(size_t)node * 16 + j4] = acc;   // self-loop init
    }
}

// scatter: agg[dst] += xw'[src]   (ONE thread per edge, no multiplies)
__global__ void k_scatter(const int* __restrict__ src, const int* __restrict__ dst) {
    int e = blockIdx.x * blockDim.x + threadIdx.x;
    int s = src[e];
    int d = dst[e];
    const float4* xp = &g_xw[(size_t)s * 16];
    float* ap = (float*)&g_agg[(size_t)d * 16];
    float4 v[16];
#pragma unroll
    for (int j = 0; j < 16; j++) v[j] = __ldg(xp + j);
#pragma unroll
    for (int j = 0; j < 16; j++) red_add_v4(ap + 4 * j, v[j]);
}

// read-only BN stats over v = dinv*agg + b
__global__ void k_stats(const float* __restrict__ bias,
                        float* __restrict__ gsum, float* __restrict__ gss) {
    int tx = threadIdx.x & 15;   // feature float4 group
    int ty = threadIdx.x >> 4;   // node sub-stride (0..15)
    float4 b4 = ((const float4*)bias)[tx];
    float4 ls = make_float4(0.f, 0.f, 0.f, 0.f);
    float4 lq = make_float4(0.f, 0.f, 0.f, 0.f);
    for (int i = blockIdx.x * 16 + ty; i < NN; i += gridDim.x * 16) {
        float di = g_dinv[i];
        float4 a = g_agg[(size_t)i * 16 + tx];
        float4 v;
        v.x = a.x * di + b4.x;
        v.y = a.y * di + b4.y;
        v.z = a.z * di + b4.z;
        v.w = a.w * di + b4.w;
        ls.x += v.x; ls.y += v.y; ls.z += v.z; ls.w += v.w;
        lq.x += v.x * v.x; lq.y += v.y * v.y; lq.z += v.z * v.z; lq.w += v.w * v.w;
    }
    atomicAdd(&gsum[4 * tx + 0], ls.x);
    atomicAdd(&gsum[4 * tx + 1], ls.y);
    atomicAdd(&gsum[4 * tx + 2], ls.z);
    atomicAdd(&gsum[4 * tx + 3], ls.w);
    atomicAdd(&gss[4 * tx + 0], lq.x);
    atomicAdd(&gss[4 * tx + 1], lq.y);
    atomicAdd(&gss[4 * tx + 2], lq.z);
    atomicAdd(&gss[4 * tx + 3], lq.w);
}

// BN params -> scale/shift
__global__ void k_bnstats(const float* __restrict__ gsum, const float* __restrict__ gss,
                          const float* __restrict__ gamma, const float* __restrict__ beta,
                          float* __restrict__ scale, float* __restrict__ shift) {
    int f = threadIdx.x;
    if (f >= HID) return;
    const float invN = 1.0f / (float)NN;
    float mu = gsum[f] * invN;
    float var = gss[f] * invN - mu * mu;
    float sc = gamma[f] * rsqrtf(var + BN_EPS);
    scale[f] = sc;
    shift[f] = beta[f] - mu * sc;
}

// v1 = dinv*agg + b1 ; h = relu(BN1(v1)) ; xw2' = (h @ W2)*dinv ; init agg = xw2'
__global__ void k_gemm2(const float* __restrict__ W, const float* __restrict__ bias) {
    __shared__ float Ws[HID * HID];
    __shared__ float sc[HID], sh[HID];
    for (int i = threadIdx.x; i < HID * HID; i += blockDim.x) Ws[i] = W[i];
    if (threadIdx.x < HID) {
        sc[threadIdx.x] = g_scale1[threadIdx.x];
        sh[threadIdx.x] = g_shift1[threadIdx.x];
    }
    __syncthreads();
    int node = blockIdx.x * blockDim.x + threadIdx.x;
    float di = g_dinv[node];

    float h[HID];
#pragma unroll
    for (int k4 = 0; k4 < HID / 4; k4++) {
        float4 a = g_agg[(size_t)node * 16 + k4];
        float4 b4 = ((const float4*)bias)[k4];
        float vx = a.x * di + b4.x;
        float vy = a.y * di + b4.y;
        float vz = a.z * di + b4.z;
        float vw = a.w * di + b4.w;
        h[4 * k4 + 0] = fmaxf(vx * sc[4 * k4 + 0] + sh[4 * k4 + 0], 0.f);
        h[4 * k4 + 1] = fmaxf(vy * sc[4 * k4 + 1] + sh[4 * k4 + 1], 0.f);
        h[4 * k4 + 2] = fmaxf(vz * sc[4 * k4 + 2] + sh[4 * k4 + 2], 0.f);
        h[4 * k4 + 3] = fmaxf(vw * sc[4 * k4 + 3] + sh[4 * k4 + 3], 0.f);
    }
#pragma unroll
    for (int j4 = 0; j4 < HID / 4; j4++) {
        float4 acc = make_float4(0.f, 0.f, 0.f, 0.f);
#pragma unroll
        for (int k = 0; k < HID; k++) {
            float hv = h[k];
            const float* w = &Ws[k * HID + 4 * j4];
            acc.x += hv * w[0]; acc.y += hv * w[1];
            acc.z += hv * w[2]; acc.w += hv * w[3];
        }
        acc.x *= di; acc.y *= di; acc.z *= di; acc.w *= di;
        g_xw[(size_t)node * 16 + j4]  = acc;
        g_agg[(size_t)node * 16 + j4] = acc;   // self-loop init for layer 2
    }
}

// v2 = dinv*agg + b2 ; h2 = relu(BN2(v2)) ; pool[batch[i]] += h2
__global__ void k_pool(const int* __restrict__ batch, const float* __restrict__ bias) {
    unsigned t = blockIdx.x * blockDim.x + threadIdx.x;
    unsigned i = t >> 4;
    unsigned j = t & 15u;
    int g = batch[i];
    float di = g_dinv[i];
    float4 a = g_agg[(size_t)i * 16 + j];
    float4 b4 = ((const float4*)bias)[j];
    float4 s4 = ((const float4*)g_scale2)[j];
    float4 h4 = ((const float4*)g_shift2)[j];
    float4 hh;
    hh.x = fmaxf((a.x * di + b4.x) * s4.x + h4.x, 0.f);
    hh.y = fmaxf((a.y * di + b4.y) * s4.y + h4.y, 0.f);
    hh.z = fmaxf((a.z * di + b4.z) * s4.z + h4.z, 0.f);
    hh.w = fmaxf((a.w * di + b4.w) * s4.w + h4.w, 0.f);
    red_add_v4(&g_pool[(size_t)g * HID + 4 * j], hh);
    if (j == 0) atomicAdd(&g_cnt[g], 1.0f);
}

// heads: one warp per graph
__global__ void k_head(const float* __restrict__ gf,
                       const float* __restrict__ Wo1, const float* __restrict__ bo1,
                       const float* __restrict__ Wo2, const float* __restrict__ bo2,
                       const float* __restrict__ Wb1, const float* __restrict__ bb1,
                       const float* __restrict__ Wb2, const float* __restrict__ bb2,
                       float* __restrict__ out) {
    int g = blockIdx.x;
    int lane = threadIdx.x;
    __shared__ float c[HID + G_FEAT];
    float inv = 1.0f / fmaxf(g_cnt[g], 1.0f);
    for (int k = lane; k < HID; k += 32) c[k] = g_pool[(size_t)g * HID + k] * inv;
    if (lane < G_FEAT) c[HID + lane] = gf[(size_t)g * G_FEAT + lane];
    __syncwarp();

    float ho = bo1[lane];
#pragma unroll 8
    for (int k = 0; k < HID + G_FEAT; k++) ho += c[k] * Wo1[k * 32 + lane];
    ho = fmaxf(ho, 0.f) * Wo2[lane];
#pragma unroll
    for (int o = 16; o; o >>= 1) ho += __shfl_xor_sync(0xffffffffu, ho, o);
    if (lane == 0) out[g] = ho + bo2[0];

    float hb = bb1[lane];
#pragma unroll 8
    for (int k = 0; k < HID + G_FEAT; k++) hb += c[k] * Wb1[k * 32 + lane];
    hb = fmaxf(hb, 0.f) * Wb2[lane];
#pragma unroll
    for (int o = 16; o; o >>= 1) hb += __shfl_xor_sync(0xffffffffu, hb, o);
    if (lane == 0) out[NG + g] = hb + bb2[0];
}

// ---------------- launch --------------------------------------------------------
extern "C" void kernel_launch(void* const* d_in, const int* in_sizes, int n_in,
                              void* d_out, int out_size) {
    const float* x      = (const float*)d_in[0];
    const int*   ei     = (const int*)d_in[1];
    const int*   batch  = (const int*)d_in[2];
    const float* gf     = (const float*)d_in[3];
    const float* W1     = (const float*)d_in[4];
    const float* b1     = (const float*)d_in[5];
    const float* gamma1 = (const float*)d_in[6];
    const float* beta1  = (const float*)d_in[7];
    const float* W2     = (const float*)d_in[8];
    const float* b2     = (const float*)d_in[9];
    const float* gamma2 = (const float*)d_in[10];
    const float* beta2  = (const float*)d_in[11];
    const float* Wo1    = (const float*)d_in[12];
    const float* bo1    = (const float*)d_in[13];
    const float* Wo2    = (const float*)d_in[14];
    const float* bo2    = (const float*)d_in[15];
    const float* Wb1    = (const float*)d_in[16];
    const float* bb1    = (const float*)d_in[17];
    const float* Wb2    = (const float*)d_in[18];
    const float* bb2    = (const float*)d_in[19];
    float* out = (float*)d_out;

    const int* src = ei;
    const int* dst = ei + NE;

    void *p_sum1, *p_ss1, *p_sum2, *p_ss2, *p_pool, *p_cnt;
    void *p_scale1, *p_shift1, *p_scale2, *p_shift2;
    cudaGetSymbolAddress(&p_sum1,  g_sum1);
    cudaGetSymbolAddress(&p_ss1,   g_ss1);
    cudaGetSymbolAddress(&p_sum2,  g_sum2);
    cudaGetSymbolAddress(&p_ss2,   g_ss2);
    cudaGetSymbolAddress(&p_pool,  g_pool);
    cudaGetSymbolAddress(&p_cnt,   g_cnt);
    cudaGetSymbolAddress(&p_scale1, g_scale1);
    cudaGetSymbolAddress(&p_shift1, g_shift1);
    cudaGetSymbolAddress(&p_scale2, g_scale2);
    cudaGetSymbolAddress(&p_shift2, g_shift2);

    cudaMemsetAsync(p_sum1, 0, sizeof(float) * HID);
    cudaMemsetAsync(p_ss1,  0, sizeof(float) * HID);
    cudaMemsetAsync(p_sum2, 0, sizeof(float) * HID);
    cudaMemsetAsync(p_ss2,  0, sizeof(float) * HID);
    cudaMemsetAsync(p_pool, 0, sizeof(float) * NG * HID);
    cudaMemsetAsync(p_cnt,  0, sizeof(float) * NG);

    // degree
    k_fill_ones<<<NN / 256, 256>>>();
    k_degree<<<NE / 256, 256>>>(dst);

    // ----- layer 1 -----
    k_gemm1<<<NN / 256, 256>>>(x, W1);                 // also converts deg->dinv, inits agg
    k_scatter<<<NE / 256, 256>>>(src, dst);
    k_stats<<<512, 256>>>(b1, (float*)p_sum1, (float*)p_ss1);
    k_bnstats<<<1, HID>>>((const float*)p_sum1, (const float*)p_ss1, gamma1, beta1,
                          (float*)p_scale1, (float*)p_shift1);

    // ----- layer 2 -----
    k_gemm2<<<NN / 128, 128>>>(W2, b1);                // reads agg(v1), writes xw2' + agg init
    k_scatter<<<NE / 256, 256>>>(src, dst);
    k_stats<<<512, 256>>>(b2, (float*)p_sum2, (float*)p_ss2);
    k_bnstats<<<1, HID>>>((const float*)p_sum2, (const float*)p_ss2, gamma2, beta2,
                          (float*)p_scale2, (float*)p_shift2);

    // ----- pool + heads -----
    k_pool<<<(NN * 16) / 256, 256>>>(batch, b2);
    k_head<<<NG, 32>>>(gf, Wo1, bo1, Wo2, bo2, Wb1, bb1, Wb2, bb2, out);
}

// round 5
// speedup vs baseline: 1.9584x; 1.9584x over previous
#include <cuda_runtime.h>
#include <cuda_bf16.h>

#define NN 131072      // nodes
#define NE 2097152     // edges
#define F_IN 32
#define HID 64
#define G_FEAT 16
#define NG 1024        // graphs
#define BN_EPS 1e-5f

// ---------------- scratch ------------------------------------------------------
__device__ int    g_deg[NN];                 // in-degree (without self loop)
__device__ int    g_start[NN];               // CSR row start
__device__ int    g_ptr[NN];                 // fill cursor
__device__ int    g_esrc[NE];                // CSR: src node per slot
__device__ int    g_bsum[512];               // block partial sums for scan
__device__ int    g_boff[512];               // exclusive block offsets
__device__ float  g_dinv[NN];                // rsqrt(deg+1)
__device__ float4 g_xw[NN * 16];             // xw' = (X@W)*dinv  (per layer)
__device__ float4 g_agg[NN * 16];            // v = dinv*(self+neigh sum) + b
__device__ float g_sum1[HID], g_ss1[HID];
__device__ float g_sum2[HID], g_ss2[HID];
__device__ float g_scale1[HID], g_shift1[HID];
__device__ float g_scale2[HID], g_shift2[HID];
__device__ float g_pool[NG * HID];
__device__ float g_cnt[NG];

// ---------------- helpers -----------------------------------------------------
__device__ __forceinline__ void red_add_v4(float* addr, float4 v) {
    asm volatile("red.global.add.v4.f32 [%0], {%1, %2, %3, %4};"
                 :: "l"(addr), "f"(v.x), "f"(v.y), "f"(v.z), "f"(v.w)
                 : "memory");
}

// ---------------- CSR build -----------------------------------------------------
__global__ void k_zero_deg() {
    int i = blockIdx.x * blockDim.x + threadIdx.x;
    g_deg[i] = 0;
}

__global__ void k_degree(const int* __restrict__ dst) {
    int e = blockIdx.x * blockDim.x + threadIdx.x;
    atomicAdd(&g_deg[dst[e]], 1);
}

// block-level inclusive scan of 256 degrees; write block-exclusive prefix + block sum
__global__ void k_scan1() {
    __shared__ int sm[256];
    int tid = threadIdx.x;
    int i = blockIdx.x * 256 + tid;
    int d = g_deg[i];
    sm[tid] = d;
    __syncthreads();
#pragma unroll
    for (int off = 1; off < 256; off <<= 1) {
        int t = (tid >= off) ? sm[tid - off] : 0;
        __syncthreads();
        sm[tid] += t;
        __syncthreads();
    }
    g_start[i] = sm[tid] - d;           // block-exclusive
    if (tid == 255) g_bsum[blockIdx.x] = sm[255];
}

// scan the 512 block sums (one block)
__global__ void k_scan2() {
    __shared__ int sm[512];
    int tid = threadIdx.x;
    int d = g_bsum[tid];
    sm[tid] = d;
    __syncthreads();
#pragma unroll
    for (int off = 1; off < 512; off <<= 1) {
        int t = (tid >= off) ? sm[tid - off] : 0;
        __syncthreads();
        sm[tid] += t;
        __syncthreads();
    }
    g_boff[tid] = sm[tid] - d;          // exclusive
}

// finalize: global start offsets, fill cursors, dinv
__global__ void k_scan3() {
    int i = blockIdx.x * blockDim.x + threadIdx.x;
    int st = g_start[i] + g_boff[i >> 8];
    g_start[i] = st;
    g_ptr[i]   = st;
    g_dinv[i]  = rsqrtf((float)g_deg[i] + 1.0f);
}

// fill CSR slots with src ids
__global__ void k_fill(const int* __restrict__ src, const int* __restrict__ dst) {
    int e = blockIdx.x * blockDim.x + threadIdx.x;
    int d = dst[e];
    int p = atomicAdd(&g_ptr[d], 1);
    g_esrc[p] = src[e];
}

// ---------------- compute kernels ----------------------------------------------

// xw' = (x @ W1) * dinv
__global__ void k_gemm1(const float* __restrict__ x, const float* __restrict__ W) {
    __shared__ float Ws[F_IN * HID];
    for (int i = threadIdx.x; i < F_IN * HID; i += blockDim.x) Ws[i] = W[i];
    __syncthreads();
    int node = blockIdx.x * blockDim.x + threadIdx.x;
    float di = g_dinv[node];

    float xr[F_IN];
    const float4* xp = (const float4*)(x + (size_t)node * F_IN);
#pragma unroll
    for (int k = 0; k < F_IN / 4; k++) {
        float4 v = xp[k];
        xr[4 * k + 0] = v.x; xr[4 * k + 1] = v.y;
        xr[4 * k + 2] = v.z; xr[4 * k + 3] = v.w;
    }
#pragma unroll
    for (int j4 = 0; j4 < HID / 4; j4++) {
        float4 acc = make_float4(0.f, 0.f, 0.f, 0.f);
#pragma unroll
        for (int k = 0; k < F_IN; k++) {
            float xv = xr[k];
            const float* w = &Ws[k * HID + 4 * j4];
            acc.x += xv * w[0]; acc.y += xv * w[1];
            acc.z += xv * w[2]; acc.w += xv * w[3];
        }
        acc.x *= di; acc.y *= di; acc.z *= di; acc.w *= di;
        g_xw[(size_t)node * 16 + j4] = acc;
    }
}

// gather: v[i] = dinv[i]*(xw'[i] + sum_{s in N(i)} xw'[s]) + b ; store to g_agg
// also accumulate BN sums (block-reduced). 16 threads per node, 16 nodes per block.
__global__ void k_gather(const float* __restrict__ bias,
                         float* __restrict__ gsum, float* __restrict__ gss) {
    __shared__ float4 sm_s[256];
    __shared__ float4 sm_q[256];
    int tid = threadIdx.x;
    int j   = tid & 15;                // float4 group
    int node = blockIdx.x * 16 + (tid >> 4);

    int st = g_start[node];
    int dg = g_deg[node];
    const int* ep = &g_esrc[st];

    float4 acc = g_xw[(size_t)node * 16 + j];   // self loop

    int k = 0;
    for (; k + 2 <= dg; k += 2) {
        int s0 = __ldg(ep + k);
        int s1 = __ldg(ep + k + 1);
        float4 v0 = __ldg(&g_xw[(size_t)s0 * 16 + j]);
        float4 v1 = __ldg(&g_xw[(size_t)s1 * 16 + j]);
        acc.x += v0.x; acc.y += v0.y; acc.z += v0.z; acc.w += v0.w;
        acc.x += v1.x; acc.y += v1.y; acc.z += v1.z; acc.w += v1.w;
    }
    if (k < dg) {
        int s0 = __ldg(ep + k);
        float4 v0 = __ldg(&g_xw[(size_t)s0 * 16 + j]);
        acc.x += v0.x; acc.y += v0.y; acc.z += v0.z; acc.w += v0.w;
    }

    float di = g_dinv[node];
    float4 b4 = ((const float4*)bias)[j];
    float4 v;
    v.x = acc.x * di + b4.x;
    v.y = acc.y * di + b4.y;
    v.z = acc.z * di + b4.z;
    v.w = acc.w * di + b4.w;
    g_agg[(size_t)node * 16 + j] = v;

    sm_s[tid] = v;
    sm_q[tid] = make_float4(v.x * v.x, v.y * v.y, v.z * v.z, v.w * v.w);
    __syncthreads();
    if (tid < 16) {
        float4 s = make_float4(0.f, 0.f, 0.f, 0.f);
        float4 q = make_float4(0.f, 0.f, 0.f, 0.f);
#pragma unroll
        for (int r = 0; r < 16; r++) {
            float4 a = sm_s[r * 16 + tid];
            float4 b = sm_q[r * 16 + tid];
            s.x += a.x; s.y += a.y; s.z += a.z; s.w += a.w;
            q.x += b.x; q.y += b.y; q.z += b.z; q.w += b.w;
        }
        atomicAdd(&gsum[4 * tid + 0], s.x);
        atomicAdd(&gsum[4 * tid + 1], s.y);
        atomicAdd(&gsum[4 * tid + 2], s.z);
        atomicAdd(&gsum[4 * tid + 3], s.w);
        atomicAdd(&gss[4 * tid + 0], q.x);
        atomicAdd(&gss[4 * tid + 1], q.y);
        atomicAdd(&gss[4 * tid + 2], q.z);
        atomicAdd(&gss[4 * tid + 3], q.w);
    }
}

// BN params -> scale/shift
__global__ void k_bnstats(const float* __restrict__ gsum, const float* __restrict__ gss,
                          const float* __restrict__ gamma, const float* __restrict__ beta,
                          float* __restrict__ scale, float* __restrict__ shift) {
    int f = threadIdx.x;
    if (f >= HID) return;
    const float invN = 1.0f / (float)NN;
    float mu = gsum[f] * invN;
    float var = gss[f] * invN - mu * mu;
    float sc = gamma[f] * rsqrtf(var + BN_EPS);
    scale[f] = sc;
    shift[f] = beta[f] - mu * sc;
}

// h = relu(v1*sc+sh) ; xw2' = (h @ W2)*dinv
__global__ void k_gemm2(const float* __restrict__ W) {
    __shared__ float Ws[HID * HID];
    __shared__ float sc[HID], sh[HID];
    for (int i = threadIdx.x; i < HID * HID; i += blockDim.x) Ws[i] = W[i];
    if (threadIdx.x < HID) {
        sc[threadIdx.x] = g_scale1[threadIdx.x];
        sh[threadIdx.x] = g_shift1[threadIdx.x];
    }
    __syncthreads();
    int node = blockIdx.x * blockDim.x + threadIdx.x;
    float di = g_dinv[node];

    float h[HID];
#pragma unroll
    for (int k4 = 0; k4 < HID / 4; k4++) {
        float4 a = g_agg[(size_t)node * 16 + k4];
        h[4 * k4 + 0] = fmaxf(a.x * sc[4 * k4 + 0] + sh[4 * k4 + 0], 0.f);
        h[4 * k4 + 1] = fmaxf(a.y * sc[4 * k4 + 1] + sh[4 * k4 + 1], 0.f);
        h[4 * k4 + 2] = fmaxf(a.z * sc[4 * k4 + 2] + sh[4 * k4 + 2], 0.f);
        h[4 * k4 + 3] = fmaxf(a.w * sc[4 * k4 + 3] + sh[4 * k4 + 3], 0.f);
    }
#pragma unroll
    for (int j4 = 0; j4 < HID / 4; j4++) {
        float4 acc = make_float4(0.f, 0.f, 0.f, 0.f);
#pragma unroll
        for (int k = 0; k < HID; k++) {
            float hv = h[k];
            const float* w = &Ws[k * HID + 4 * j4];
            acc.x += hv * w[0]; acc.y += hv * w[1];
            acc.z += hv * w[2]; acc.w += hv * w[3];
        }
        acc.x *= di; acc.y *= di; acc.z *= di; acc.w *= di;
        g_xw[(size_t)node * 16 + j4] = acc;
    }
}

// h2 = relu(v2*sc2+sh2) ; pool[batch[i]] += h2 ; cnt
__global__ void k_pool(const int* __restrict__ batch) {
    unsigned t = blockIdx.x * blockDim.x + threadIdx.x;
    unsigned i = t >> 4;
    unsigned j = t & 15u;
    int g = batch[i];
    float4 a = g_agg[(size_t)i * 16 + j];
    float4 s4 = ((const float4*)g_scale2)[j];
    float4 h4 = ((const float4*)g_shift2)[j];
    float4 hh;
    hh.x = fmaxf(a.x * s4.x + h4.x, 0.f);
    hh.y = fmaxf(a.y * s4.y + h4.y, 0.f);
    hh.z = fmaxf(a.z * s4.z + h4.z, 0.f);
    hh.w = fmaxf(a.w * s4.w + h4.w, 0.f);
    red_add_v4(&g_pool[(size_t)g * HID + 4 * j], hh);
    if (j == 0) atomicAdd(&g_cnt[g], 1.0f);
}

// heads: one warp per graph
__global__ void k_head(const float* __restrict__ gf,
                       const float* __restrict__ Wo1, const float* __restrict__ bo1,
                       const float* __restrict__ Wo2, const float* __restrict__ bo2,
                       const float* __restrict__ Wb1, const float* __restrict__ bb1,
                       const float* __restrict__ Wb2, const float* __restrict__ bb2,
                       float* __restrict__ out) {
    int g = blockIdx.x;
    int lane = threadIdx.x;
    __shared__ float c[HID + G_FEAT];
    float inv = 1.0f / fmaxf(g_cnt[g], 1.0f);
    for (int k = lane; k < HID; k += 32) c[k] = g_pool[(size_t)g * HID + k] * inv;
    if (lane < G_FEAT) c[HID + lane] = gf[(size_t)g * G_FEAT + lane];
    __syncwarp();

    float ho = bo1[lane];
#pragma unroll 8
    for (int k = 0; k < HID + G_FEAT; k++) ho += c[k] * Wo1[k * 32 + lane];
    ho = fmaxf(ho, 0.f) * Wo2[lane];
#pragma unroll
    for (int o = 16; o; o >>= 1) ho += __shfl_xor_sync(0xffffffffu, ho, o);
    if (lane == 0) out[g] = ho + bo2[0];

    float hb = bb1[lane];
#pragma unroll 8
    for (int k = 0; k < HID + G_FEAT; k++) hb += c[k] * Wb1[k * 32 + lane];
    hb = fmaxf(hb, 0.f) * Wb2[lane];
#pragma unroll
    for (int o = 16; o; o >>= 1) hb += __shfl_xor_sync(0xffffffffu, hb, o);
    if (lane == 0) out[NG + g] = hb + bb2[0];
}

// ---------------- launch --------------------------------------------------------
extern "C" void kernel_launch(void* const* d_in, const int* in_sizes, int n_in,
                              void* d_out, int out_size) {
    const float* x      = (const float*)d_in[0];
    const int*   ei     = (const int*)d_in[1];
    const int*   batch  = (const int*)d_in[2];
    const float* gf     = (const float*)d_in[3];
    const float* W1     = (const float*)d_in[4];
    const float* b1     = (const float*)d_in[5];
    const float* gamma1 = (const float*)d_in[6];
    const float* beta1  = (const float*)d_in[7];
    const float* W2     = (const float*)d_in[8];
    const float* b2     = (const float*)d_in[9];
    const float* gamma2 = (const float*)d_in[10];
    const float* beta2  = (const float*)d_in[11];
    const float* Wo1    = (const float*)d_in[12];
    const float* bo1    = (const float*)d_in[13];
    const float* Wo2    = (const float*)d_in[14];
    const float* bo2    = (const float*)d_in[15];
    const float* Wb1    = (const float*)d_in[16];
    const float* bb1    = (const float*)d_in[17];
    const float* Wb2    = (const float*)d_in[18];
    const float* bb2    = (const float*)d_in[19];
    float* out = (float*)d_out;

    const int* src = ei;
    const int* dst = ei + NE;

    void *p_sum1, *p_ss1, *p_sum2, *p_ss2, *p_pool, *p_cnt;
    void *p_scale1, *p_shift1, *p_scale2, *p_shift2;
    cudaGetSymbolAddress(&p_sum1,  g_sum1);
    cudaGetSymbolAddress(&p_ss1,   g_ss1);
    cudaGetSymbolAddress(&p_sum2,  g_sum2);
    cudaGetSymbolAddress(&p_ss2,   g_ss2);
    cudaGetSymbolAddress(&p_pool,  g_pool);
    cudaGetSymbolAddress(&p_cnt,   g_cnt);
    cudaGetSymbolAddress(&p_scale1, g_scale1);
    cudaGetSymbolAddress(&p_shift1, g_shift1);
    cudaGetSymbolAddress(&p_scale2, g_scale2);
    cudaGetSymbolAddress(&p_shift2, g_shift2);

    cudaMemsetAsync(p_sum1, 0, sizeof(float) * HID);
    cudaMemsetAsync(p_ss1,  0, sizeof(float) * HID);
    cudaMemsetAsync(p_sum2, 0, sizeof(float) * HID);
    cudaMemsetAsync(p_ss2,  0, sizeof(float) * HID);
    cudaMemsetAsync(p_pool, 0, sizeof(float) * NG * HID);
    cudaMemsetAsync(p_cnt,  0, sizeof(float) * NG);

    // ----- CSR build -----
    k_zero_deg<<<NN / 256, 256>>>();
    k_degree<<<NE / 256, 256>>>(dst);
    k_scan1<<<NN / 256, 256>>>();
    k_scan2<<<1, 512>>>();
    k_scan3<<<NN / 256, 256>>>();
    k_fill<<<NE / 256, 256>>>(src, dst);

    // ----- layer 1 -----
    k_gemm1<<<NN / 256, 256>>>(x, W1);
    k_gather<<<NN / 16, 256>>>(b1, (float*)p_sum1, (float*)p_ss1);
    k_bnstats<<<1, HID>>>((const float*)p_sum1, (const float*)p_ss1, gamma1, beta1,
                          (float*)p_scale1, (float*)p_shift1);

    // ----- layer 2 -----
    k_gemm2<<<NN / 128, 128>>>(W2);
    k_gather<<<NN / 16, 256>>>(b2, (float*)p_sum2, (float*)p_ss2);
    k_bnstats<<<1, HID>>>((const float*)p_sum2, (const float*)p_ss2, gamma2, beta2,
                          (float*)p_scale2, (float*)p_shift2);

    // ----- pool + heads -----
    k_pool<<<(NN * 16) / 256, 256>>>(batch);
    k_head<<<NG, 32>>>(gf, Wo1, bo1, Wo2, bo2, Wb1, bb1, Wb2, bb2, out);
}

// round 7
// speedup vs baseline: 3.6535x; 1.8655x over previous
#include <cuda_runtime.h>
#include <cuda_bf16.h>

#define NN 131072      // nodes
#define NE 2097152     // edges
#define F_IN 32
#define HID 64
#define G_FEAT 16
#define NG 1024        // graphs
#define BN_EPS 1e-5f
#define NSLOT 256      // BN partial slots

// ---------------- scratch ------------------------------------------------------
__device__ int    g_deg[NN];                 // in-degree (without self loop)
__device__ int    g_start[NN];               // CSR row start
__device__ int    g_ptr[NN];                 // fill cursor
__device__ int    g_esrc[NE];                // CSR: src node per slot
__device__ int    g_bsum[512];               // block partial sums for scan
__device__ int    g_boff[512];               // exclusive block offsets
__device__ float  g_dinv[NN];                // rsqrt(deg+1)
__device__ float4 g_xw[NN * 16];             // xw' = (X@W)*dinv  (per layer)
__device__ float4 g_agg[NN * 16];            // v = dinv*(self+neigh sum) + b
__device__ float g_psum1[NSLOT * HID], g_pss1[NSLOT * HID];
__device__ float g_psum2[NSLOT * HID], g_pss2[NSLOT * HID];
__device__ float g_scale1[HID], g_shift1[HID];
__device__ float g_scale2[HID], g_shift2[HID];
__device__ float g_pool[NG * HID];
__device__ float g_cnt[NG];

// ---------------- helpers -----------------------------------------------------
__device__ __forceinline__ void red_add_v4(float* addr, float4 v) {
    asm volatile("red.global.add.v4.f32 [%0], {%1, %2, %3, %4};"
                 :: "l"(addr), "f"(v.x), "f"(v.y), "f"(v.z), "f"(v.w)
                 : "memory");
}
__device__ __forceinline__ void red_add_v2(float* addr, float2 v) {
    asm volatile("red.global.add.v2.f32 [%0], {%1, %2};"
                 :: "l"(addr), "f"(v.x), "f"(v.y)
                 : "memory");
}

// ---------------- CSR build -----------------------------------------------------
__global__ void k_degree(const int* __restrict__ dst) {
    int e = blockIdx.x * blockDim.x + threadIdx.x;
    atomicAdd(&g_deg[dst[e]], 1);
}

__global__ void k_scan1() {
    __shared__ int sm[256];
    int tid = threadIdx.x;
    int i = blockIdx.x * 256 + tid;
    int d = g_deg[i];
    sm[tid] = d;
    __syncthreads();
#pragma unroll
    for (int off = 1; off < 256; off <<= 1) {
        int t = (tid >= off) ? sm[tid - off] : 0;
        __syncthreads();
        sm[tid] += t;
        __syncthreads();
    }
    g_start[i] = sm[tid] - d;
    if (tid == 255) g_bsum[blockIdx.x] = sm[255];
}

__global__ void k_scan2() {
    __shared__ int sm[512];
    int tid = threadIdx.x;
    int d = g_bsum[tid];
    sm[tid] = d;
    __syncthreads();
#pragma unroll
    for (int off = 1; off < 512; off <<= 1) {
        int t = (tid >= off) ? sm[tid - off] : 0;
        __syncthreads();
        sm[tid] += t;
        __syncthreads();
    }
    g_boff[tid] = sm[tid] - d;
}

__global__ void k_scan3() {
    int i = blockIdx.x * blockDim.x + threadIdx.x;
    int st = g_start[i] + g_boff[i >> 8];
    g_start[i] = st;
    g_ptr[i]   = st;
    g_dinv[i]  = rsqrtf((float)g_deg[i] + 1.0f);
}

__global__ void k_fill(const int* __restrict__ src, const int* __restrict__ dst) {
    int e = blockIdx.x * blockDim.x + threadIdx.x;
    int d = dst[e];
    int p = atomicAdd(&g_ptr[d], 1);
    g_esrc[p] = src[e];
}

// ---------------- compute kernels ----------------------------------------------

// xw' = (x @ W1) * dinv
__global__ void k_gemm1(const float* __restrict__ x, const float* __restrict__ W) {
    __shared__ float Ws[F_IN * HID];
    for (int i = threadIdx.x; i < F_IN * HID; i += blockDim.x) Ws[i] = W[i];
    __syncthreads();
    int node = blockIdx.x * blockDim.x + threadIdx.x;
    float di = g_dinv[node];

    float xr[F_IN];
    const float4* xp = (const float4*)(x + (size_t)node * F_IN);
#pragma unroll
    for (int k = 0; k < F_IN / 4; k++) {
        float4 v = xp[k];
        xr[4 * k + 0] = v.x; xr[4 * k + 1] = v.y;
        xr[4 * k + 2] = v.z; xr[4 * k + 3] = v.w;
    }
#pragma unroll
    for (int j4 = 0; j4 < HID / 4; j4++) {
        float4 acc = make_float4(0.f, 0.f, 0.f, 0.f);
#pragma unroll
        for (int k = 0; k < F_IN; k++) {
            float xv = xr[k];
            const float* w = &Ws[k * HID + 4 * j4];
            acc.x += xv * w[0]; acc.y += xv * w[1];
            acc.z += xv * w[2]; acc.w += xv * w[3];
        }
        acc.x *= di; acc.y *= di; acc.z *= di; acc.w *= di;
        g_xw[(size_t)node * 16 + j4] = acc;
    }
}

// gather: one warp per node. v = dinv*(self + sum neigh) + b -> g_agg
// BN partials block-reduced into spread slots.
__global__ void k_gather(const float* __restrict__ bias,
                         float* __restrict__ psum, float* __restrict__ pss) {
    __shared__ int    sidx[8][32];
    __shared__ float2 ssum[8][32];
    __shared__ float2 ssq[8][32];
    int tid = threadIdx.x;
    int warp = tid >> 5, lane = tid & 31;
    int node = blockIdx.x * 8 + warp;

    int st = g_start[node];
    int dg = g_deg[node];
    const int* ep = &g_esrc[st];
    const float2* XW = (const float2*)g_xw;

    float2 acc = XW[(size_t)node * 32 + lane];   // self loop

    for (int k0 = 0; k0 < dg; k0 += 32) {
        int nb = dg - k0; if (nb > 32) nb = 32;
        int my = (lane < nb) ? __ldg(ep + k0 + lane) : 0;
        sidx[warp][lane] = my;
        __syncwarp();
        int e = 0;
        for (; e + 4 <= nb; e += 4) {
            int s0 = sidx[warp][e + 0];
            int s1 = sidx[warp][e + 1];
            int s2 = sidx[warp][e + 2];
            int s3 = sidx[warp][e + 3];
            float2 v0 = __ldg(&XW[(size_t)s0 * 32 + lane]);
            float2 v1 = __ldg(&XW[(size_t)s1 * 32 + lane]);
            float2 v2 = __ldg(&XW[(size_t)s2 * 32 + lane]);
            float2 v3 = __ldg(&XW[(size_t)s3 * 32 + lane]);
            acc.x += v0.x + v1.x + v2.x + v3.x;
            acc.y += v0.y + v1.y + v2.y + v3.y;
        }
        for (; e < nb; e++) {
            int s0 = sidx[warp][e];
            float2 v0 = __ldg(&XW[(size_t)s0 * 32 + lane]);
            acc.x += v0.x; acc.y += v0.y;
        }
        __syncwarp();
    }

    float di = g_dinv[node];
    float2 b2 = ((const float2*)bias)[lane];
    float2 v = make_float2(acc.x * di + b2.x, acc.y * di + b2.y);
    ((float2*)g_agg)[(size_t)node * 32 + lane] = v;

    ssum[warp][lane] = v;
    ssq[warp][lane]  = make_float2(v.x * v.x, v.y * v.y);
    __syncthreads();
    if (warp == 0) {
        float2 s = make_float2(0.f, 0.f), q = make_float2(0.f, 0.f);
#pragma unroll
        for (int r = 0; r < 8; r++) {
            float2 a = ssum[r][lane]; s.x += a.x; s.y += a.y;
            float2 b = ssq[r][lane];  q.x += b.x; q.y += b.y;
        }
        int slot = blockIdx.x & (NSLOT - 1);
        red_add_v2(&psum[slot * HID + 2 * lane], s);
        red_add_v2(&pss[slot * HID + 2 * lane], q);
    }
}

// reduce partial slots -> scale/shift   (1 block, 64 threads)
__global__ void k_bnstats(const float* __restrict__ psum, const float* __restrict__ pss,
                          const float* __restrict__ gamma, const float* __restrict__ beta,
                          float* __restrict__ scale, float* __restrict__ shift) {
    int f = threadIdx.x;
    float s = 0.f, q = 0.f;
#pragma unroll 8
    for (int r = 0; r < NSLOT; r++) {
        s += psum[r * HID + f];
        q += pss[r * HID + f];
    }
    const float invN = 1.0f / (float)NN;
    float mu = s * invN;
    float var = q * invN - mu * mu;
    float sc = gamma[f] * rsqrtf(var + BN_EPS);
    scale[f] = sc;
    shift[f] = beta[f] - mu * sc;
}

// tiled: h = relu(v1*sc+sh) ; xw2' = (h @ W2)*dinv
// block: 256 threads, tile = 64 nodes x 64 cols, thread = 4x4 micro-tile
__global__ void k_gemm2(const float* __restrict__ W) {
    __shared__ float hs[64 * 65];     // [node][k] padded
    __shared__ float ws[64 * 64];     // [k][col]
    __shared__ float sc[HID], sh[HID];
    int tid = threadIdx.x;

    if (tid < HID) { sc[tid] = g_scale1[tid]; sh[tid] = g_shift1[tid]; }
    for (int i = tid; i < 64 * 64; i += 256) ws[i] = W[i];
    __syncthreads();

    // load agg tile (fully coalesced), compute h, store transposed-by-feature
    const float4* ag = (const float4*)g_agg + (size_t)blockIdx.x * 1024;
#pragma unroll
    for (int it = 0; it < 4; it++) {
        int i = tid + it * 256;           // float4 index in tile (0..1023)
        int node = i >> 4, q = i & 15;
        float4 a = ag[i];
        float h0 = fmaxf(a.x * sc[4 * q + 0] + sh[4 * q + 0], 0.f);
        float h1 = fmaxf(a.y * sc[4 * q + 1] + sh[4 * q + 1], 0.f);
        float h2 = fmaxf(a.z * sc[4 * q + 2] + sh[4 * q + 2], 0.f);
        float h3 = fmaxf(a.w * sc[4 * q + 3] + sh[4 * q + 3], 0.f);
        float* hp = &hs[node * 65];
        hp[4 * q + 0] = h0; hp[4 * q + 1] = h1;
        hp[4 * q + 2] = h2; hp[4 * q + 3] = h3;
    }
    __syncthreads();

    int tx = tid & 15, ty = tid >> 4;
    float acc[4][4] = {};
#pragma unroll 16
    for (int k = 0; k < 64; k++) {
        float4 wv = *(const float4*)&ws[k * 64 + 4 * tx];
        float h0 = hs[(4 * ty + 0) * 65 + k];
        float h1 = hs[(4 * ty + 1) * 65 + k];
        float h2 = hs[(4 * ty + 2) * 65 + k];
        float h3 = hs[(4 * ty + 3) * 65 + k];
        acc[0][0] += h0 * wv.x; acc[0][1] += h0 * wv.y; acc[0][2] += h0 * wv.z; acc[0][3] += h0 * wv.w;
        acc[1][0] += h1 * wv.x; acc[1][1] += h1 * wv.y; acc[1][2] += h1 * wv.z; acc[1][3] += h1 * wv.w;
        acc[2][0] += h2 * wv.x; acc[2][1] += h2 * wv.y; acc[2][2] += h2 * wv.z; acc[2][3] += h2 * wv.w;
        acc[3][0] += h3 * wv.x; acc[3][1] += h3 * wv.y; acc[3][2] += h3 * wv.z; acc[3][3] += h3 * wv.w;
    }

    int node0 = blockIdx.x * 64 + 4 * ty;
#pragma unroll
    for (int i = 0; i < 4; i++) {
        float di = g_dinv[node0 + i];
        g_xw[(size_t)(node0 + i) * 16 + tx] =
            make_float4(acc[i][0] * di, acc[i][1] * di, acc[i][2] * di, acc[i][3] * di);
    }
}

// h2 = relu(v2*sc2+sh2) ; pool[batch[i]] += h2 ; cnt
__global__ void k_pool(const int* __restrict__ batch) {
    unsigned t = blockIdx.x * blockDim.x + threadIdx.x;
    unsigned i = t >> 4;
    unsigned j = t & 15u;
    int g = batch[i];
    float4 a = g_agg[(size_t)i * 16 + j];
    float4 s4 = ((const float4*)g_scale2)[j];
    float4 h4 = ((const float4*)g_shift2)[j];
    float4 hh;
    hh.x = fmaxf(a.x * s4.x + h4.x, 0.f);
    hh.y = fmaxf(a.y * s4.y + h4.y, 0.f);
    hh.z = fmaxf(a.z * s4.z + h4.z, 0.f);
    hh.w = fmaxf(a.w * s4.w + h4.w, 0.f);
    red_add_v4(&g_pool[(size_t)g * HID + 4 * j], hh);
    if (j == 0) atomicAdd(&g_cnt[g], 1.0f);
}

// heads: one warp per graph
__global__ void k_head(const float* __restrict__ gf,
                       const float* __restrict__ Wo1, const float* __restrict__ bo1,
                       const float* __restrict__ Wo2, const float* __restrict__ bo2,
                       const float* __restrict__ Wb1, const float* __restrict__ bb1,
                       const float* __restrict__ Wb2, const float* __restrict__ bb2,
                       float* __restrict__ out) {
    int g = blockIdx.x;
    int lane = threadIdx.x;
    __shared__ float c[HID + G_FEAT];
    float inv = 1.0f / fmaxf(g_cnt[g], 1.0f);
    for (int k = lane; k < HID; k += 32) c[k] = g_pool[(size_t)g * HID + k] * inv;
    if (lane < G_FEAT) c[HID + lane] = gf[(size_t)g * G_FEAT + lane];
    __syncwarp();

    float ho = bo1[lane];
#pragma unroll 8
    for (int k = 0; k < HID + G_FEAT; k++) ho += c[k] * Wo1[k * 32 + lane];
    ho = fmaxf(ho, 0.f) * Wo2[lane];
#pragma unroll
    for (int o = 16; o; o >>= 1) ho += __shfl_xor_sync(0xffffffffu, ho, o);
    if (lane == 0) out[g] = ho + bo2[0];

    float hb = bb1[lane];
#pragma unroll 8
    for (int k = 0; k < HID + G_FEAT; k++) hb += c[k] * Wb1[k * 32 + lane];
    hb = fmaxf(hb, 0.f) * Wb2[lane];
#pragma unroll
    for (int o = 16; o; o >>= 1) hb += __shfl_xor_sync(0xffffffffu, hb, o);
    if (lane == 0) out[NG + g] = hb + bb2[0];
}

// ---------------- launch --------------------------------------------------------
extern "C" void kernel_launch(void* const* d_in, const int* in_sizes, int n_in,
                              void* d_out, int out_size) {
    const float* x      = (const float*)d_in[0];
    const int*   ei     = (const int*)d_in[1];
    const int*   batch  = (const int*)d_in[2];
    const float* gf     = (const float*)d_in[3];
    const float* W1     = (const float*)d_in[4];
    const float* b1     = (const float*)d_in[5];
    const float* gamma1 = (const float*)d_in[6];
    const float* beta1  = (const float*)d_in[7];
    const float* W2     = (const float*)d_in[8];
    const float* b2     = (const float*)d_in[9];
    const float* gamma2 = (const float*)d_in[10];
    const float* beta2  = (const float*)d_in[11];
    const float* Wo1    = (const float*)d_in[12];
    const float* bo1    = (const float*)d_in[13];
    const float* Wo2    = (const float*)d_in[14];
    const float* bo2    = (const float*)d_in[15];
    const float* Wb1    = (const float*)d_in[16];
    const float* bb1    = (const float*)d_in[17];
    const float* Wb2    = (const float*)d_in[18];
    const float* bb2    = (const float*)d_in[19];
    float* out = (float*)d_out;

    const int* src = ei;
    const int* dst = ei + NE;

    void *p_deg, *p_ps1, *p_pq1, *p_ps2, *p_pq2, *p_pool, *p_cnt;
    void *p_scale1, *p_shift1, *p_scale2, *p_shift2;
    cudaGetSymbolAddress(&p_deg,  g_deg);
    cudaGetSymbolAddress(&p_ps1,  g_psum1);
    cudaGetSymbolAddress(&p_pq1,  g_pss1);
    cudaGetSymbolAddress(&p_ps2,  g_psum2);
    cudaGetSymbolAddress(&p_pq2,  g_pss2);
    cudaGetSymbolAddress(&p_pool, g_pool);
    cudaGetSymbolAddress(&p_cnt,  g_cnt);
    cudaGetSymbolAddress(&p_scale1, g_scale1);
    cudaGetSymbolAddress(&p_shift1, g_shift1);
    cudaGetSymbolAddress(&p_scale2, g_scale2);
    cudaGetSymbolAddress(&p_shift2, g_shift2);

    cudaMemsetAsync(p_deg,  0, sizeof(int) * NN);
    cudaMemsetAsync(p_ps1,  0, sizeof(float) * NSLOT * HID);
    cudaMemsetAsync(p_pq1,  0, sizeof(float) * NSLOT * HID);
    cudaMemsetAsync(p_ps2,  0, sizeof(float) * NSLOT * HID);
    cudaMemsetAsync(p_pq2,  0, sizeof(float) * NSLOT * HID);
    cudaMemsetAsync(p_pool, 0, sizeof(float) * NG * HID);
    cudaMemsetAsync(p_cnt,  0, sizeof(float) * NG);

    // ----- CSR build -----
    k_degree<<<NE / 256, 256>>>(dst);
    k_scan1<<<NN / 256, 256>>>();
    k_scan2<<<1, 512>>>();
    k_scan3<<<NN / 256, 256>>>();
    k_fill<<<NE / 256, 256>>>(src, dst);

    // ----- layer 1 -----
    k_gemm1<<<NN / 256, 256>>>(x, W1);
    k_gather<<<NN / 8, 256>>>(b1, (float*)p_ps1, (float*)p_pq1);
    k_bnstats<<<1, HID>>>((const float*)p_ps1, (const float*)p_pq1, gamma1, beta1,
                          (float*)p_scale1, (float*)p_shift1);

    // ----- layer 2 -----
    k_gemm2<<<NN / 64, 256>>>(W2);
    k_gather<<<NN / 8, 256>>>(b2, (float*)p_ps2, (float*)p_pq2);
    k_bnstats<<<1, HID>>>((const float*)p_ps2, (const float*)p_pq2, gamma2, beta2,
                          (float*)p_scale2, (float*)p_shift2);

    // ----- pool + heads -----
    k_pool<<<(NN * 16) / 256, 256>>>(batch);
    k_head<<<NG, 32>>>(gf, Wo1, bo1, Wo2, bo2, Wb1, bb1, Wb2, bb2, out);
}